// round 7
// baseline (speedup 1.0000x reference)
#include <cuda_runtime.h>

// ---------------------------------------------------------------------------
// MeanPooling: out[b,:] = mean of x[i,:] over rows i with batch[i]==b
// x: (N,128) fp32, batch: (N,) sorted int64-or-int32, out: (4096,128) fp32
// R6: counts-first design. k_pre: binary-search per-segment counts on the
// sorted batch (4096 x 2 searches), publish g_inv[b]=1/max(cnt,1), zero out.
// k_accum: segmented warp reduction; flush = atomicAdd(acc * g_inv[seg])
// straight into d_out. No sums scratch, no divide epilogue, no barriers.
// g_inv is fully overwritten by k_pre each replay -> deterministic.
// ---------------------------------------------------------------------------

#define D 128
#define MAXB 8192

__device__ float g_inv[MAXB];     // 1/max(count,1) per segment

// Detect dtype of batch buffer. Reads only within the first n 32-bit words
// (in-bounds for both layouts). int64 LE: odd words are high halves == 0
// (values < 4096). int32 sorted data: tail words ~ num_graphs-1 (nonzero).
__device__ __forceinline__ int detect_is64(const unsigned int* __restrict__ w,
                                           int n) {
    int top = n - 1;
    if ((top & 1) == 0) top--;          // largest odd index <= n-1
    int nz = 0;
#pragma unroll 1
    for (int k = 0; k < 32; k++) {
        int idx = top - 2 * k;
        if (idx < 1) break;
        if (w[idx] != 0u) { nz = 1; break; }
    }
    return (nz == 0) ? 1 : 0;
}

// first index i in [0,n) with batch[i] >= key  (batch sorted ascending)
__device__ __forceinline__ int lower_bound_seg(const int* __restrict__ bw,
                                               int ish, int n, int key) {
    int lo = 0, hi = n;
    while (lo < hi) {
        int mid = (lo + hi) >> 1;
        if (bw[mid << ish] < key) lo = mid + 1;
        else hi = mid;
    }
    return lo;
}

// k_pre: zero out (float4/thread) + compute g_inv via binary searches.
__global__ void __launch_bounds__(256) k_pre(const void* __restrict__ batch,
                                             float4* __restrict__ out,
                                             int n, int n4, int nb) {
    int gid = blockIdx.x * blockDim.x + threadIdx.x;
    if (gid < n4)
        out[gid] = make_float4(0.f, 0.f, 0.f, 0.f);
    if (gid < nb) {
        const int is64 = detect_is64((const unsigned int*)batch, n);
        const int* bw = (const int*)batch;
        const int ish = is64 ? 1 : 0;
        int s0 = lower_bound_seg(bw, ish, n, gid);
        int s1 = lower_bound_seg(bw, ish, n, gid + 1);
        float c = (float)(s1 - s0);
        g_inv[gid] = __frcp_rn(fmaxf(c, 1.0f));
    }
}

__device__ __forceinline__ void flush_seg(float* __restrict__ out, int seg,
                                          int lane, const float4& acc) {
    float rinv = g_inv[seg];
    float* p = out + (size_t)seg * D + lane * 4;
    atomicAdd(p + 0, acc.x * rinv);
    atomicAdd(p + 1, acc.y * rinv);
    atomicAdd(p + 2, acc.z * rinv);
    atomicAdd(p + 3, acc.w * rinv);
}

__global__ void __launch_bounds__(256, 6) k_accum(const float4* __restrict__ x4,
                                                  const void* __restrict__ batch,
                                                  float* __restrict__ out,
                                                  int n) {
    const int lane = threadIdx.x & 31;
    const int wid = (blockIdx.x << 3) + (threadIdx.x >> 5);
    const int tw = gridDim.x << 3;
    const int per = (n + tw - 1) / tw;
    int r0 = wid * per;
    int r1 = min(r0 + per, n);
    if (r0 >= r1) return;

    const int is64 = detect_is64((const unsigned int*)batch, n);
    const int* bw = (const int*)batch;
    const int ish = is64 ? 1 : 0;   // int64 LE: low word at bw[2i]

    float4 acc = make_float4(0.f, 0.f, 0.f, 0.f);
    int cur = bw[r0 << ish];

    int r = r0;
    // 4 rows per iteration; all 4 float4 loads issued before the boundary
    // branch (streaming hint: x has no reuse).
    for (; r + 4 <= r1; r += 4) {
        const float4* p = x4 + (size_t)r * 32 + lane;
        float4 v0 = __ldcs(p);
        float4 v1 = __ldcs(p + 32);
        float4 v2 = __ldcs(p + 64);
        float4 v3 = __ldcs(p + 96);
        int blast = bw[(r + 3) << ish];
        if (blast == cur) {
            acc.x += v0.x + v1.x + v2.x + v3.x;
            acc.y += v0.y + v1.y + v2.y + v3.y;
            acc.z += v0.z + v1.z + v2.z + v3.z;
            acc.w += v0.w + v1.w + v2.w + v3.w;
        } else {
            float4 v[4] = {v0, v1, v2, v3};
#pragma unroll
            for (int k = 0; k < 4; k++) {
                int b = bw[(r + k) << ish];
                if (b != cur) {
                    flush_seg(out, cur, lane, acc);
                    acc = make_float4(0.f, 0.f, 0.f, 0.f);
                    cur = b;
                }
                acc.x += v[k].x; acc.y += v[k].y;
                acc.z += v[k].z; acc.w += v[k].w;
            }
        }
    }
    // Tail rows
    for (; r < r1; r++) {
        int b = bw[r << ish];
        if (b != cur) {
            flush_seg(out, cur, lane, acc);
            acc = make_float4(0.f, 0.f, 0.f, 0.f);
            cur = b;
        }
        float4 v = __ldcs(x4 + (size_t)r * 32 + lane);
        acc.x += v.x; acc.y += v.y; acc.z += v.z; acc.w += v.w;
    }
    flush_seg(out, cur, lane, acc);
}

extern "C" void kernel_launch(void* const* d_in, const int* in_sizes, int n_in,
                              void* d_out, int out_size) {
    const float* x = (const float*)d_in[0];
    const void* batch = d_in[1];

    int n = in_sizes[0] / D;               // number of rows
    int n4 = out_size / 4;                 // float4 elements in output
    int nb = out_size / D;                 // number of segments
    if (nb > MAXB) nb = MAXB;
    float* out = (float*)d_out;

    k_pre<<<(n4 + 255) / 256, 256>>>(batch, (float4*)out, n, n4, nb);
    k_accum<<<888, 256>>>((const float4*)x, batch, out, n);
}

// round 8
// speedup vs baseline: 1.0195x; 1.0195x over previous
#include <cuda_runtime.h>

// ---------------------------------------------------------------------------
// MeanPooling: out[b,:] = mean of x[i,:] over rows i with batch[i]==b
// x: (N,128) fp32, batch: (N,) sorted int64-or-int32, out: (4096,128) fp32
// R7: R4 structure + dynamic warp-level work stealing in k_accum (atomic
// ticket, 128-row chunks) to reclaim the multi-CTA spread tail. Ticket and
// scratch are reset in k_div -> every graph replay starts clean (BSS zero).
// ---------------------------------------------------------------------------

#define D 128
#define MAXB 8192
#define MAXOUT (MAXB * D)
#define CHUNK 128          // rows per stolen work item

__device__ float g_sums[MAXOUT];  // accumulation scratch; zero before+after
__device__ int g_counts[MAXB];    // per-segment row counts; zero before+after
__device__ int g_ticket;          // work-stealing counter; reset in k_div

// Detect dtype of batch buffer. Reads only within the first n 32-bit words
// (in-bounds for both layouts). int64 LE: odd words are high halves == 0
// (values < 4096). int32 sorted data: tail words ~ num_graphs-1 (nonzero).
__device__ __forceinline__ int detect_is64(const unsigned int* __restrict__ w,
                                           int n) {
    int top = n - 1;
    if ((top & 1) == 0) top--;          // largest odd index <= n-1
    int nz = 0;
#pragma unroll 1
    for (int k = 0; k < 32; k++) {
        int idx = top - 2 * k;
        if (idx < 1) break;
        if (w[idx] != 0u) { nz = 1; break; }
    }
    return (nz == 0) ? 1 : 0;
}

__device__ __forceinline__ void flush_seg(int seg, int lane,
                                          const float4& acc, int cnt) {
    float* p = g_sums + (size_t)seg * D + lane * 4;
    atomicAdd(p + 0, acc.x);
    atomicAdd(p + 1, acc.y);
    atomicAdd(p + 2, acc.z);
    atomicAdd(p + 3, acc.w);
    if (lane == 0) atomicAdd(&g_counts[seg], cnt);
}

__global__ void __launch_bounds__(256, 6) k_accum(const float4* __restrict__ x4,
                                                  const void* __restrict__ batch,
                                                  int n) {
    const int lane = threadIdx.x & 31;

    const int is64 = detect_is64((const unsigned int*)batch, n);
    const int* bw = (const int*)batch;
    const int ish = is64 ? 1 : 0;   // int64 LE: low word at bw[2i]

    const int nchunks = (n + CHUNK - 1) / CHUNK;

    for (;;) {
        // warp grabs the next chunk of sorted rows
        int c;
        if (lane == 0) c = atomicAdd(&g_ticket, 1);
        c = __shfl_sync(0xFFFFFFFFu, c, 0);
        if (c >= nchunks) break;

        int r0 = c * CHUNK;
        int r1 = min(r0 + CHUNK, n);

        float4 acc = make_float4(0.f, 0.f, 0.f, 0.f);
        int cur = bw[r0 << ish];
        int cnt = 0;

        int r = r0;
        // 4 rows per iteration; all 4 float4 loads issued before the
        // boundary branch (streaming hint: x has no reuse).
        for (; r + 4 <= r1; r += 4) {
            const float4* p = x4 + (size_t)r * 32 + lane;
            float4 v0 = __ldcs(p);
            float4 v1 = __ldcs(p + 32);
            float4 v2 = __ldcs(p + 64);
            float4 v3 = __ldcs(p + 96);
            int blast = bw[(r + 3) << ish];
            if (blast == cur) {
                acc.x += v0.x + v1.x + v2.x + v3.x;
                acc.y += v0.y + v1.y + v2.y + v3.y;
                acc.z += v0.z + v1.z + v2.z + v3.z;
                acc.w += v0.w + v1.w + v2.w + v3.w;
                cnt += 4;
            } else {
                float4 v[4] = {v0, v1, v2, v3};
#pragma unroll
                for (int k = 0; k < 4; k++) {
                    int b = bw[(r + k) << ish];
                    if (b != cur) {
                        flush_seg(cur, lane, acc, cnt);
                        acc = make_float4(0.f, 0.f, 0.f, 0.f);
                        cnt = 0;
                        cur = b;
                    }
                    acc.x += v[k].x; acc.y += v[k].y;
                    acc.z += v[k].z; acc.w += v[k].w;
                    cnt++;
                }
            }
        }
        // Tail rows of this chunk
        for (; r < r1; r++) {
            int b = bw[r << ish];
            if (b != cur) {
                flush_seg(cur, lane, acc, cnt);
                acc = make_float4(0.f, 0.f, 0.f, 0.f);
                cnt = 0;
                cur = b;
            }
            float4 v = __ldcs(x4 + (size_t)r * 32 + lane);
            acc.x += v.x; acc.y += v.y; acc.z += v.z; acc.w += v.w;
            cnt++;
        }
        flush_seg(cur, lane, acc, cnt);
    }
}

// Finalize (vectorized): out4 = sums4 * (1/max(count,1)); re-zero scratch and
// the work-stealing ticket so the next graph replay starts clean.
__global__ void __launch_bounds__(256) k_div(float4* __restrict__ out,
                                             int n4) {
    int i = blockIdx.x * blockDim.x + threadIdx.x;
    if (i >= n4) return;
    int seg = i >> 5;                    // (i*4) / 128
    float c = (float)g_counts[seg];
    float rinv = __frcp_rn(fmaxf(c, 1.0f));
    float4* s4 = (float4*)g_sums;
    float4 v = s4[i];
    v.x *= rinv; v.y *= rinv; v.z *= rinv; v.w *= rinv;
    out[i] = v;
    s4[i] = make_float4(0.f, 0.f, 0.f, 0.f);
    if ((i & 31) == 0) g_counts[seg] = 0;
    if (i == 0) g_ticket = 0;
}

extern "C" void kernel_launch(void* const* d_in, const int* in_sizes, int n_in,
                              void* d_out, int out_size) {
    const float* x = (const float*)d_in[0];
    const void* batch = d_in[1];

    int n = in_sizes[0] / D;               // number of rows
    int n4 = out_size / 4;                 // float4 elements in output

    k_accum<<<888, 256>>>((const float4*)x, batch, n);
    k_div<<<(n4 + 255) / 256, 256>>>((float4*)d_out, n4);
}

// round 10
// speedup vs baseline: 1.1195x; 1.0981x over previous
#include <cuda_runtime.h>

// ---------------------------------------------------------------------------
// MeanPooling: out[b,:] = mean of x[i,:] over rows i with batch[i]==b
// x: (N,128) fp32, batch: (N,) sorted int64-or-int32, out: (4096,128) fp32
// R8: exact R4 kernels (best so far) + PDL on k_div: the divide kernel is
// launched with programmatic stream serialization so its ramp overlaps
// k_accum's drain; cudaGridDependencySynchronize() gates the scratch reads.
// ---------------------------------------------------------------------------

#define D 128
#define MAXB 8192
#define MAXOUT (MAXB * D)

__device__ float g_sums[MAXOUT];  // accumulation scratch; zero before+after
__device__ int g_counts[MAXB];    // per-segment row counts; zero before+after

// Detect dtype of batch buffer. Reads only within the first n 32-bit words
// (in-bounds for both layouts). int64 LE: odd words are high halves == 0
// (values < 4096). int32 sorted data: tail words ~ num_graphs-1 (nonzero).
__device__ __forceinline__ int detect_is64(const unsigned int* __restrict__ w,
                                           int n) {
    int top = n - 1;
    if ((top & 1) == 0) top--;          // largest odd index <= n-1
    int nz = 0;
#pragma unroll 1
    for (int k = 0; k < 32; k++) {
        int idx = top - 2 * k;
        if (idx < 1) break;
        if (w[idx] != 0u) { nz = 1; break; }
    }
    return (nz == 0) ? 1 : 0;
}

__device__ __forceinline__ void flush_seg(int seg, int lane,
                                          const float4& acc, int cnt) {
    float* p = g_sums + (size_t)seg * D + lane * 4;
    atomicAdd(p + 0, acc.x);
    atomicAdd(p + 1, acc.y);
    atomicAdd(p + 2, acc.z);
    atomicAdd(p + 3, acc.w);
    if (lane == 0) atomicAdd(&g_counts[seg], cnt);
}

__global__ void __launch_bounds__(256, 6) k_accum(const float4* __restrict__ x4,
                                                  const void* __restrict__ batch,
                                                  int n) {
    const int lane = threadIdx.x & 31;
    const int wid = (blockIdx.x << 3) + (threadIdx.x >> 5);
    const int tw = gridDim.x << 3;
    const int per = (n + tw - 1) / tw;
    int r0 = wid * per;
    int r1 = min(r0 + per, n);
    if (r0 >= r1) return;

    const int is64 = detect_is64((const unsigned int*)batch, n);
    const int* bw = (const int*)batch;
    const int ish = is64 ? 1 : 0;   // int64 LE: low word at bw[2i]

    float4 acc = make_float4(0.f, 0.f, 0.f, 0.f);
    int cur = bw[r0 << ish];
    int cnt = 0;

    int r = r0;
    // 4 rows per iteration; all 4 float4 loads issued before the boundary
    // branch (streaming hint: x has no reuse).
    for (; r + 4 <= r1; r += 4) {
        const float4* p = x4 + (size_t)r * 32 + lane;
        float4 v0 = __ldcs(p);
        float4 v1 = __ldcs(p + 32);
        float4 v2 = __ldcs(p + 64);
        float4 v3 = __ldcs(p + 96);
        int blast = bw[(r + 3) << ish];
        if (blast == cur) {
            acc.x += v0.x + v1.x + v2.x + v3.x;
            acc.y += v0.y + v1.y + v2.y + v3.y;
            acc.z += v0.z + v1.z + v2.z + v3.z;
            acc.w += v0.w + v1.w + v2.w + v3.w;
            cnt += 4;
        } else {
            float4 v[4] = {v0, v1, v2, v3};
#pragma unroll
            for (int k = 0; k < 4; k++) {
                int b = bw[(r + k) << ish];
                if (b != cur) {
                    flush_seg(cur, lane, acc, cnt);
                    acc = make_float4(0.f, 0.f, 0.f, 0.f);
                    cnt = 0;
                    cur = b;
                }
                acc.x += v[k].x; acc.y += v[k].y;
                acc.z += v[k].z; acc.w += v[k].w;
                cnt++;
            }
        }
    }
    // Tail rows
    for (; r < r1; r++) {
        int b = bw[r << ish];
        if (b != cur) {
            flush_seg(cur, lane, acc, cnt);
            acc = make_float4(0.f, 0.f, 0.f, 0.f);
            cnt = 0;
            cur = b;
        }
        float4 v = __ldcs(x4 + (size_t)r * 32 + lane);
        acc.x += v.x; acc.y += v.y; acc.z += v.z; acc.w += v.w;
        cnt++;
    }
    flush_seg(cur, lane, acc, cnt);
}

// Finalize (vectorized, PDL): wait for k_accum's memory flush, then
// out4 = sums4 * (1/max(count,1)); re-zero scratch so the next graph replay
// starts clean (BSS starts zero -> deterministic across replays).
__global__ void __launch_bounds__(256) k_div(float4* __restrict__ out,
                                             int n4) {
#if __CUDA_ARCH__ >= 900
    cudaGridDependencySynchronize();
#endif
    int i = blockIdx.x * blockDim.x + threadIdx.x;
    if (i >= n4) return;
    int seg = i >> 5;                    // (i*4) / 128
    float c = (float)g_counts[seg];
    float rinv = __frcp_rn(fmaxf(c, 1.0f));
    float4* s4 = (float4*)g_sums;
    float4 v = s4[i];
    v.x *= rinv; v.y *= rinv; v.z *= rinv; v.w *= rinv;
    out[i] = v;
    s4[i] = make_float4(0.f, 0.f, 0.f, 0.f);
    if ((i & 31) == 0) g_counts[seg] = 0;
}

extern "C" void kernel_launch(void* const* d_in, const int* in_sizes, int n_in,
                              void* d_out, int out_size) {
    const float* x = (const float*)d_in[0];
    const void* batch = d_in[1];

    int n = in_sizes[0] / D;               // number of rows
    int n4 = out_size / 4;                 // float4 elements in output

    k_accum<<<888, 256>>>((const float4*)x, batch, n);

    // Launch k_div with Programmatic Stream Serialization so its prologue
    // overlaps k_accum's drain; cudaGridDependencySynchronize() inside the
    // kernel enforces the data dependency.
    cudaLaunchConfig_t cfg = {};
    cfg.gridDim = dim3((unsigned)((n4 + 255) / 256));
    cfg.blockDim = dim3(256);
    cfg.dynamicSmemBytes = 0;
    cfg.stream = 0;                        // legacy default stream (captured)
    cudaLaunchAttribute attr[1];
    attr[0].id = cudaLaunchAttributeProgrammaticStreamSerialization;
    attr[0].val.programmaticStreamSerializationAllowed = 1;
    cfg.attrs = attr;
    cfg.numAttrs = 1;
    cudaError_t e = cudaLaunchKernelEx(&cfg, k_div, (float4*)d_out, n4);
    if (e != cudaSuccess) {
        // Fallback: plain launch (keeps correctness if PDL capture refused)
        k_div<<<(n4 + 255) / 256, 256>>>((float4*)d_out, n4);
    }
}